// round 16
// baseline (speedup 1.0000x reference)
#include <cuda_runtime.h>
#include <cuda_fp16.h>

#define BSZ 4
#define NSQ 16384
#define SSAMP 8
#define CPL 64
#define RESOL 128
#define HWSZ (RESOL * RESOL)
#define IND 192
#define NPTS (BSZ * NSQ)   // 65536

// ---------------- scratch (static device globals; no allocation) ----------------
__device__ __align__(16) float  g_planesf[(size_t)BSZ * 3 * HWSZ * CPL]; // fp32 channel-last
__device__ __align__(16) __half g_planesh[(size_t)BSZ * 3 * HWSZ * CPL]; // fp16 channel-last
__device__ __align__(16) float  g_feat[(size_t)NPTS * IND];
__device__ __align__(16) float  g_offwt[(size_t)NPTS * 32];              // 24 off + 8 wt
__device__ __align__(16) __half g_auxwh[(size_t)NPTS * IND];             // fp16, PERMUTED frag order
__device__ float  g_wtsum[NPTS];
__device__ __align__(16) __half g_Wc_hi[IND * IND];                      // Wout@Wv (fp16)
__device__ float g_bvout[IND];                                           // Wout@b_v
__device__ __align__(16) __half g_Wow_hi[32 * IND];                      // [Woff;Wwt] packed
__device__ __align__(16) __half g_Wow_lo[32 * IND];
__device__ float g_bow[32];

// ---------------- 1) transpose planes to channel-last (fp32 + fp16) ----------------
// grid (HW/128, B, 3), block 256
__global__ __launch_bounds__(256) void transpose_planes(const float* __restrict__ pxz,
                                                        const float* __restrict__ pxy,
                                                        const float* __restrict__ pyz) {
    int p = blockIdx.z;
    int b = blockIdx.y;
    int yx0 = blockIdx.x * 128;
    const float* src = (p == 0 ? pxz : (p == 1 ? pxy : pyz)) + (size_t)b * CPL * HWSZ;
    float* dstf = g_planesf + (size_t)(b * 3 + p) * HWSZ * CPL;
    __half* dsth = g_planesh + (size_t)(b * 3 + p) * HWSZ * CPL;

    __shared__ float tile[CPL][132];
    int t = threadIdx.x;
    int tx = t & 31, ty = t >> 5;
#pragma unroll
    for (int cb = 0; cb < CPL; cb += 8) {
        int c = cb + ty;
        float4 v = *(const float4*)(src + (size_t)c * HWSZ + yx0 + tx * 4);
        *(float4*)(&tile[c][tx * 4]) = v;
    }
    __syncthreads();
#pragma unroll
    for (int i = 0; i < 4; i++) {
        int e = i * 256 + t;
        int c8 = e >> 7, yxl = e & 127;
        float v[8];
#pragma unroll
        for (int j = 0; j < 8; j++) v[j] = tile[c8 * 8 + j][yxl];
        size_t off = (size_t)(yx0 + yxl) * CPL + c8 * 8;
        *(float4*)(dstf + off) = make_float4(v[0], v[1], v[2], v[3]);
        *(float4*)(dstf + off + 4) = make_float4(v[4], v[5], v[6], v[7]);
    }
#pragma unroll
    for (int i = 0; i < 2; i++) {
        int e = i * 256 + t;
        int c16 = e >> 7, yxl = e & 127;
        uint4 u0, u1;
        __half2* hp0 = (__half2*)&u0;
        __half2* hp1 = (__half2*)&u1;
#pragma unroll
        for (int j = 0; j < 4; j++) {
            hp0[j] = __floats2half2_rn(tile[c16 * 16 + 2 * j][yxl],
                                       tile[c16 * 16 + 2 * j + 1][yxl]);
            hp1[j] = __floats2half2_rn(tile[c16 * 16 + 8 + 2 * j][yxl],
                                       tile[c16 * 16 + 9 + 2 * j][yxl]);
        }
        size_t off = (size_t)(yx0 + yxl) * CPL + c16 * 16;
        *(uint4*)(dsth + off) = u0;
        *(uint4*)(dsth + off + 8) = u1;
    }
}

// ---------------- 1b) merged weight prep: wcomb + off/wt split + bvout + bow -----
// grid IND (192 blocks), block IND (192 threads)
__global__ __launch_bounds__(192) void prep_weights(
    const float* __restrict__ Wout, const float* __restrict__ Wv,
    const float* __restrict__ Woff, const float* __restrict__ bo,
    const float* __restrict__ Wwt, const float* __restrict__ bw,
    const float* __restrict__ bv) {
    __shared__ float wrow[IND];
    int m = blockIdx.x, k = threadIdx.x;
    wrow[k] = Wout[m * IND + k];
    __syncthreads();
    float s = 0.0f;
#pragma unroll 4
    for (int n = 0; n < IND; n++) s += wrow[n] * Wv[n * IND + k];
    g_Wc_hi[m * IND + k] = __float2half_rn(s);

    int gid = m * IND + k;
    if (gid < 32 * IND) {
        int n = gid / IND, kk = gid - n * IND;
        float v = (n < 24) ? Woff[n * IND + kk] : Wwt[(n - 24) * IND + kk];
        __half h = __float2half_rn(v);
        g_Wow_hi[gid] = h;
        g_Wow_lo[gid] = __float2half_rn(v - __half2float(h));
    }
    if (gid < 32) g_bow[gid] = (gid < 24) ? bo[gid] : bw[gid - 24];
    if (gid < IND) {
        float sb = 0.0f;
        for (int n = 0; n < IND; n++) sb += Wout[gid * IND + n] * bv[n];
        g_bvout[gid] = sb;
    }
}

// ---------------- bilinear corner weights ----------------
__device__ __forceinline__ void bilerp_setup(float u, float v, int& i00, int& i01,
                                             int& i10, int& i11, float& w00, float& w01,
                                             float& w10, float& w11) {
    float x = __saturatef(u) * 127.0f;
    float y = __saturatef(v) * 127.0f;
    float xf = floorf(x), yf = floorf(y);
    int ix0 = (int)xf, iy0 = (int)yf;
    int ix1 = min(ix0 + 1, 127), iy1 = min(iy0 + 1, 127);
    float wx = x - xf, wy = y - yf;
    w00 = (1.0f - wx) * (1.0f - wy);
    w01 = wx * (1.0f - wy);
    w10 = (1.0f - wx) * wy;
    w11 = wx * wy;
    i00 = iy0 * RESOL + ix0; i01 = iy0 * RESOL + ix1;
    i10 = iy1 * RESOL + ix0; i11 = iy1 * RESOL + ix1;
}

// ---------------- 2) sample features at query points (fp32 planes) ----------------
__global__ __launch_bounds__(256) void sample_query(const float* __restrict__ qp) {
    int gid = blockIdx.x * 256 + threadIdx.x;
    int pt = gid / 24, lane = gid - pt * 24;
    int c8 = lane * 8;
    int p = c8 >> 6, ch = c8 & 63;
    int b = pt >> 14;
    float px = qp[pt * 3 + 0], py = qp[pt * 3 + 1], pz = qp[pt * 3 + 2];
    float u = (p == 2) ? py : px;
    float v = (p == 1) ? py : pz;
    int i00, i01, i10, i11;
    float w00, w01, w10, w11;
    bilerp_setup(u, v, i00, i01, i10, i11, w00, w01, w10, w11);
    const float* base = g_planesf + (size_t)(b * 3 + p) * HWSZ * CPL + ch;
    float acc[8];
#pragma unroll
    for (int h = 0; h < 2; h++) {
        float4 f00 = *(const float4*)(base + (size_t)i00 * CPL + 4 * h);
        float4 f01 = *(const float4*)(base + (size_t)i01 * CPL + 4 * h);
        float4 f10 = *(const float4*)(base + (size_t)i10 * CPL + 4 * h);
        float4 f11 = *(const float4*)(base + (size_t)i11 * CPL + 4 * h);
        acc[4 * h + 0] = w00 * f00.x + w01 * f01.x + w10 * f10.x + w11 * f11.x;
        acc[4 * h + 1] = w00 * f00.y + w01 * f01.y + w10 * f10.y + w11 * f11.y;
        acc[4 * h + 2] = w00 * f00.z + w01 * f01.z + w10 * f10.z + w11 * f11.z;
        acc[4 * h + 3] = w00 * f00.w + w01 * f01.w + w10 * f10.w + w11 * f11.w;
    }
    float4* o = (float4*)(g_feat + (size_t)pt * IND + c8);
    o[0] = make_float4(acc[0], acc[1], acc[2], acc[3]);
    o[1] = make_float4(acc[4], acc[5], acc[6], acc[7]);
}

// ---------------- MMA helpers ----------------
__device__ __forceinline__ void mma16816(float* c, const unsigned* a, const unsigned* b) {
    asm volatile(
        "mma.sync.aligned.m16n8k16.row.col.f32.f16.f16.f32 "
        "{%0,%1,%2,%3}, {%4,%5,%6,%7}, {%8,%9}, {%0,%1,%2,%3};\n"
        : "+f"(c[0]), "+f"(c[1]), "+f"(c[2]), "+f"(c[3])
        : "r"(a[0]), "r"(a[1]), "r"(a[2]), "r"(a[3]), "r"(b[0]), "r"(b[1]));
}
__device__ __forceinline__ void split2(float2 v, unsigned& hi, unsigned& lo) {
    __half2 h = __floats2half2_rn(v.x, v.y);
    float2 hf = __half22float2(h);
    __half2 l = __floats2half2_rn(v.x - hf.x, v.y - hf.y);
    hi = *(unsigned*)&h;
    lo = *(unsigned*)&l;
}
__device__ __forceinline__ void load_a_raw(const float* p, float2* buf) {
    buf[0] = *(const float2*)(p);
    buf[1] = *(const float2*)(p + 8 * IND);
    buf[2] = *(const float2*)(p + 8);
    buf[3] = *(const float2*)(p + 8 * IND + 8);
}

// ---------------- 3) off+wt predictor via split-fp16 MMA (smem B, dbuf A) --------
// POSITION PATH: keeps all 3 MMA terms (fp32-grade). M=NPTS, N=32, K=192.
__global__ __launch_bounds__(256) void predict_offwt_mma() {
    __shared__ __half Bs[2][32 * IND];   // [hi/lo][n][k], 4B-word XOR swizzle
    int tid = threadIdx.x, wid = tid >> 5, lane = tid & 31;
    int g = lane >> 2, t = lane & 3;
    int m_base = blockIdx.x * 256 + wid * 32;

    for (int idx = tid; idx < 32 * 24; idx += 256) {
        int n = idx / 24, c8 = idx - n * 24;
        int pw = (c8 * 4) ^ ((n & 7) << 2);
        int hoff = n * IND + (pw << 1);
        *(uint4*)(&Bs[0][hoff]) = *(const uint4*)(g_Wow_hi + (size_t)n * IND + c8 * 8);
        *(uint4*)(&Bs[1][hoff]) = *(const uint4*)(g_Wow_lo + (size_t)n * IND + c8 * 8);
    }
    __syncthreads();

    float c[2][4][4] = {};
    const float* Ap = g_feat + (size_t)(m_base + g) * IND + 2 * t;

    float2 abuf[2][2][4];
    load_a_raw(Ap, abuf[0][0]);
    load_a_raw(Ap + 16 * IND, abuf[0][1]);

    for (int kt = 0; kt < 12; kt++) {
        int cur = kt & 1;
        if (kt < 11) {
            int k1 = (kt + 1) * 16;
            load_a_raw(Ap + k1, abuf[cur ^ 1][0]);
            load_a_raw(Ap + 16 * IND + k1, abuf[cur ^ 1][1]);
        }
        int k0 = kt * 16;
        unsigned ah[2][4], al[2][4], bh[4][2], bl[4][2];
#pragma unroll
        for (int ms = 0; ms < 2; ms++)
#pragma unroll
            for (int i = 0; i < 4; i++)
                split2(abuf[cur][ms][i], ah[ms][i], al[ms][i]);
        int w0 = (k0 >> 1) + t;
#pragma unroll
        for (int ns = 0; ns < 4; ns++) {
            int n = ns * 8 + g;
            int sw = (n & 7) << 2;
            int h0 = n * IND + ((w0 ^ sw) << 1);
            int h1 = n * IND + (((w0 + 4) ^ sw) << 1);
            bh[ns][0] = *(const unsigned*)(&Bs[0][h0]);
            bh[ns][1] = *(const unsigned*)(&Bs[0][h1]);
            bl[ns][0] = *(const unsigned*)(&Bs[1][h0]);
            bl[ns][1] = *(const unsigned*)(&Bs[1][h1]);
        }
#pragma unroll
        for (int ms = 0; ms < 2; ms++)
#pragma unroll
            for (int ns = 0; ns < 4; ns++) {
                mma16816(c[ms][ns], ah[ms], bh[ns]);
                mma16816(c[ms][ns], ah[ms], bl[ns]);
                mma16816(c[ms][ns], al[ms], bh[ns]);
            }
    }

#pragma unroll
    for (int ms = 0; ms < 2; ms++) {
        int r0 = m_base + ms * 16 + g;
        int r1 = r0 + 8;
#pragma unroll
        for (int ns = 0; ns < 4; ns++) {
            int nc = ns * 8 + 2 * t;
            float b0 = g_bow[nc], b1 = g_bow[nc + 1];
            *(float2*)(g_offwt + (size_t)r0 * 32 + nc) =
                make_float2(c[ms][ns][0] + b0, c[ms][ns][1] + b1);
            *(float2*)(g_offwt + (size_t)r1 * 32 + nc) =
                make_float2(c[ms][ns][2] + b0, c[ms][ns][3] + b1);
        }
    }
}

// ---------------- 4) sample offset points (fp16 planes), smem offwt+qp -----------
// block 192 threads = 8 points x 24 lanes; fp16 output in PERMUTED frag order.
// minBlocks=8 forces regs<=42 -> 1536 threads/SM (occupancy is the binding lever).
__global__ __launch_bounds__(192, 8) void sample_aux(const float* __restrict__ qp) {
    __shared__ float4 sow4[64];          // 8 points x 32 floats
    __shared__ float sqp[24];            // 8 points x 3 coords
    int tid = threadIdx.x;
    int pt0 = blockIdx.x * 8;
    if (tid < 64) sow4[tid] = ((const float4*)(g_offwt + (size_t)pt0 * 32))[tid];
    if (tid >= 64 && tid < 88) sqp[tid - 64] = qp[pt0 * 3 + (tid - 64)];
    __syncthreads();
    const float* sow = (const float*)sow4;

    int pi = tid / 24, lane = tid - pi * 24;
    int pt = pt0 + pi;
    int c8 = lane * 8;
    int p = c8 >> 6, ch = c8 & 63;
    int b = pt >> 14;
    float px = sqp[pi * 3 + 0], py = sqp[pi * 3 + 1], pz = sqp[pi * 3 + 2];
    const float* ow = sow + pi * 32;

    const __half* base = g_planesh + (size_t)(b * 3 + p) * HWSZ * CPL + ch;
    float acc[8] = {};
#pragma unroll
    for (int s = 0; s < SSAMP; s++) {
        float qx = px + ow[s * 3 + 0];
        float qy = py + ow[s * 3 + 1];
        float qz = pz + ow[s * 3 + 2];
        float wgt = ow[24 + s];
        float u = (p == 2) ? qy : qx;
        float v = (p == 1) ? qy : qz;
        int i00, i01, i10, i11;
        float w00, w01, w10, w11;
        bilerp_setup(u, v, i00, i01, i10, i11, w00, w01, w10, w11);
        w00 *= wgt; w01 *= wgt; w10 *= wgt; w11 *= wgt;
        uint4 q00 = *(const uint4*)(base + (size_t)i00 * CPL);
        uint4 q01 = *(const uint4*)(base + (size_t)i01 * CPL);
        uint4 q10 = *(const uint4*)(base + (size_t)i10 * CPL);
        uint4 q11 = *(const uint4*)(base + (size_t)i11 * CPL);
        const __half2* h00 = (const __half2*)&q00;
        const __half2* h01 = (const __half2*)&q01;
        const __half2* h10 = (const __half2*)&q10;
        const __half2* h11 = (const __half2*)&q11;
#pragma unroll
        for (int i = 0; i < 4; i++) {
            float2 f00 = __half22float2(h00[i]);
            float2 f01 = __half22float2(h01[i]);
            float2 f10 = __half22float2(h10[i]);
            float2 f11 = __half22float2(h11[i]);
            acc[2 * i + 0] += w00 * f00.x + w01 * f01.x + w10 * f10.x + w11 * f11.x;
            acc[2 * i + 1] += w00 * f00.y + w01 * f01.y + w10 * f10.y + w11 * f11.y;
        }
    }
    // permuted fp16 store: element offsets blk+half + {0,1},{4,5},{8,9},{12,13}
    {
        int blk = c8 & ~15;
        int half = (c8 & 8) ? 2 : 0;
        __half* o = g_auxwh + (size_t)pt * IND + blk + half;
#pragma unroll
        for (int i = 0; i < 4; i++)
            *(__half2*)(o + 4 * i) = __floats2half2_rn(acc[2 * i], acc[2 * i + 1]);
    }
    if (lane == 0) {
        float wts = 0.0f;
#pragma unroll
        for (int s = 0; s < SSAMP; s++) wts += ow[24 + s];
        g_wtsum[pt] = wts;
    }
}

// ---------------- 5) fused GEMM: out = auxw@Wc^T + wts*bvout + bout + feat --------
// VALUE PATH: single MMA pass, A pre-rounded fp16 (R13-exact mainloop).
__global__ __launch_bounds__(256) void gemm_comb(const float* __restrict__ bout,
                                                 float* __restrict__ outF) {
    __shared__ __half Bs[64 * IND];
    int tid = threadIdx.x, wid = tid >> 5, lane = tid & 31;
    int g = lane >> 2, t = lane & 3;
    int m_base = blockIdx.x * 128 + (wid >> 1) * 32;
    int n_blk = blockIdx.y * 64;
    int nloc = (wid & 1) * 32;

    for (int idx = tid; idx < 64 * 24; idx += 256) {
        int n = idx / 24, c8 = idx - n * 24;
        int pw = (c8 * 4) ^ ((n & 7) << 2);
        int hoff = n * IND + (pw << 1);
        *(uint4*)(&Bs[hoff]) =
            *(const uint4*)(g_Wc_hi + (size_t)(n_blk + n) * IND + c8 * 8);
    }
    __syncthreads();

    float c[2][4][4] = {};
    const __half* Ap = g_auxwh + (size_t)(m_base + g) * IND + 4 * t;

    uint2 abuf[2][2];
    abuf[0][0] = *(const uint2*)(Ap);
    abuf[0][1] = *(const uint2*)(Ap + 16 * IND);

    for (int kt = 0; kt < 12; kt++) {
        int cur = kt & 1;
        if (kt < 11) {
            int k1 = (kt + 1) * 16;
            abuf[cur ^ 1][0] = *(const uint2*)(Ap + k1);
            abuf[cur ^ 1][1] = *(const uint2*)(Ap + 16 * IND + k1);
        }
        int k0 = kt * 16;
        unsigned ah[2][4], bh[4][2];
#pragma unroll
        for (int ms = 0; ms < 2; ms++) {
            ah[ms][0] = abuf[cur][ms].x;
            ah[ms][2] = abuf[cur][ms].y;
        }
        {
            uint2 r8a = *(const uint2*)(Ap + 8 * IND + k0);
            uint2 r8b = *(const uint2*)(Ap + 24 * IND + k0);
            ah[0][1] = r8a.x; ah[0][3] = r8a.y;
            ah[1][1] = r8b.x; ah[1][3] = r8b.y;
        }
        int w0 = (k0 >> 1) + t;
#pragma unroll
        for (int ns = 0; ns < 4; ns++) {
            int n = nloc + ns * 8 + g;
            int sw = (n & 7) << 2;
            int h0 = n * IND + ((w0 ^ sw) << 1);
            int h1 = n * IND + (((w0 + 4) ^ sw) << 1);
            bh[ns][0] = *(const unsigned*)(&Bs[h0]);
            bh[ns][1] = *(const unsigned*)(&Bs[h1]);
        }
#pragma unroll
        for (int ms = 0; ms < 2; ms++)
#pragma unroll
            for (int ns = 0; ns < 4; ns++)
                mma16816(c[ms][ns], ah[ms], bh[ns]);
    }

    int n_base = n_blk + nloc;
#pragma unroll
    for (int ms = 0; ms < 2; ms++) {
        int r0 = m_base + ms * 16 + g;
        int r1 = r0 + 8;
        float rs0 = g_wtsum[r0], rs1 = g_wtsum[r1];
#pragma unroll
        for (int ns = 0; ns < 4; ns++) {
            int nc = n_base + ns * 8 + 2 * t;
            float bo0 = bout[nc], bo1 = bout[nc + 1];
            float bv0 = g_bvout[nc], bv1 = g_bvout[nc + 1];
            size_t o0 = (size_t)r0 * IND + nc;
            size_t o1 = (size_t)r1 * IND + nc;
            float2 f0 = *(const float2*)(g_feat + o0);
            float2 f1 = *(const float2*)(g_feat + o1);
            *(float2*)(outF + o0) = make_float2(
                c[ms][ns][0] + bv0 * rs0 + bo0 + f0.x,
                c[ms][ns][1] + bv1 * rs0 + bo1 + f0.y);
            *(float2*)(outF + o1) = make_float2(
                c[ms][ns][2] + bv0 * rs1 + bo0 + f1.x,
                c[ms][ns][3] + bv1 * rs1 + bo1 + f1.y);
        }
    }
}

// ---------------- launch ----------------
extern "C" void kernel_launch(void* const* d_in, const int* in_sizes, int n_in,
                              void* d_out, int out_size) {
    const float* qp    = (const float*)d_in[0];
    const float* fxz   = (const float*)d_in[1];
    const float* fxy   = (const float*)d_in[2];
    const float* fyz   = (const float*)d_in[3];
    const float* W_v   = (const float*)d_in[4];
    const float* b_v   = (const float*)d_in[5];
    const float* W_out = (const float*)d_in[6];
    const float* b_out = (const float*)d_in[7];
    const float* W_off = (const float*)d_in[8];
    const float* b_off = (const float*)d_in[9];
    const float* W_wt  = (const float*)d_in[10];
    const float* b_wt  = (const float*)d_in[11];
    float* out = (float*)d_out;

    transpose_planes<<<dim3(HWSZ / 128, BSZ, 3), 256>>>(fxz, fxy, fyz);
    prep_weights<<<IND, IND>>>(W_out, W_v, W_off, b_off, W_wt, b_wt, b_v);
    sample_query<<<NPTS * 24 / 256, 256>>>(qp);
    predict_offwt_mma<<<NPTS / 256, 256>>>();
    sample_aux<<<NPTS / 8, 192>>>(qp);
    gemm_comb<<<dim3(NPTS / 128, 3), 256>>>(b_out, out);
}

// round 17
// speedup vs baseline: 1.0115x; 1.0115x over previous
#include <cuda_runtime.h>
#include <cuda_fp16.h>

#define BSZ 4
#define NSQ 16384
#define SSAMP 8
#define CPL 64
#define RESOL 128
#define HWSZ (RESOL * RESOL)
#define IND 192
#define NPTS (BSZ * NSQ)   // 65536

// ---------------- scratch (static device globals; no allocation) ----------------
__device__ __align__(16) float  g_planesf[(size_t)BSZ * 3 * HWSZ * CPL]; // fp32 channel-last
__device__ __align__(16) __half g_planesh[(size_t)BSZ * 3 * HWSZ * CPL]; // fp16 channel-last
__device__ __align__(16) float  g_feat[(size_t)NPTS * IND];
__device__ __align__(16) float  g_offwt[(size_t)NPTS * 32];              // 24 off + 8 wt
__device__ __align__(16) __half g_auxwh[(size_t)NPTS * IND];             // fp16, PERMUTED frag order
__device__ float  g_wtsum[NPTS];
__device__ __align__(16) __half g_Wc_hi[IND * IND];                      // Wout@Wv (fp16)
__device__ float g_bvout[IND];                                           // Wout@b_v
__device__ __align__(16) __half g_Wow_hi[32 * IND];                      // [Woff;Wwt] packed
__device__ __align__(16) __half g_Wow_lo[32 * IND];
__device__ float g_bow[32];

// ---------------- 1) transpose planes to channel-last (fp32 + fp16) ----------------
// grid (HW/128, B, 3), block 256
__global__ __launch_bounds__(256) void transpose_planes(const float* __restrict__ pxz,
                                                        const float* __restrict__ pxy,
                                                        const float* __restrict__ pyz) {
    int p = blockIdx.z;
    int b = blockIdx.y;
    int yx0 = blockIdx.x * 128;
    const float* src = (p == 0 ? pxz : (p == 1 ? pxy : pyz)) + (size_t)b * CPL * HWSZ;
    float* dstf = g_planesf + (size_t)(b * 3 + p) * HWSZ * CPL;
    __half* dsth = g_planesh + (size_t)(b * 3 + p) * HWSZ * CPL;

    __shared__ float tile[CPL][132];
    int t = threadIdx.x;
    int tx = t & 31, ty = t >> 5;
#pragma unroll
    for (int cb = 0; cb < CPL; cb += 8) {
        int c = cb + ty;
        float4 v = *(const float4*)(src + (size_t)c * HWSZ + yx0 + tx * 4);
        *(float4*)(&tile[c][tx * 4]) = v;
    }
    __syncthreads();
#pragma unroll
    for (int i = 0; i < 4; i++) {
        int e = i * 256 + t;
        int c8 = e >> 7, yxl = e & 127;
        float v[8];
#pragma unroll
        for (int j = 0; j < 8; j++) v[j] = tile[c8 * 8 + j][yxl];
        size_t off = (size_t)(yx0 + yxl) * CPL + c8 * 8;
        *(float4*)(dstf + off) = make_float4(v[0], v[1], v[2], v[3]);
        *(float4*)(dstf + off + 4) = make_float4(v[4], v[5], v[6], v[7]);
    }
#pragma unroll
    for (int i = 0; i < 2; i++) {
        int e = i * 256 + t;
        int c16 = e >> 7, yxl = e & 127;
        uint4 u0, u1;
        __half2* hp0 = (__half2*)&u0;
        __half2* hp1 = (__half2*)&u1;
#pragma unroll
        for (int j = 0; j < 4; j++) {
            hp0[j] = __floats2half2_rn(tile[c16 * 16 + 2 * j][yxl],
                                       tile[c16 * 16 + 2 * j + 1][yxl]);
            hp1[j] = __floats2half2_rn(tile[c16 * 16 + 8 + 2 * j][yxl],
                                       tile[c16 * 16 + 9 + 2 * j][yxl]);
        }
        size_t off = (size_t)(yx0 + yxl) * CPL + c16 * 16;
        *(uint4*)(dsth + off) = u0;
        *(uint4*)(dsth + off + 8) = u1;
    }
}

// ---------------- 1b) merged weight prep: wcomb + off/wt split + bvout + bow -----
// grid IND (192 blocks), block IND (192 threads)
__global__ __launch_bounds__(192) void prep_weights(
    const float* __restrict__ Wout, const float* __restrict__ Wv,
    const float* __restrict__ Woff, const float* __restrict__ bo,
    const float* __restrict__ Wwt, const float* __restrict__ bw,
    const float* __restrict__ bv) {
    __shared__ float wrow[IND];
    int m = blockIdx.x, k = threadIdx.x;
    wrow[k] = Wout[m * IND + k];
    __syncthreads();
    float s = 0.0f;
#pragma unroll 4
    for (int n = 0; n < IND; n++) s += wrow[n] * Wv[n * IND + k];
    g_Wc_hi[m * IND + k] = __float2half_rn(s);

    int gid = m * IND + k;
    if (gid < 32 * IND) {
        int n = gid / IND, kk = gid - n * IND;
        float v = (n < 24) ? Woff[n * IND + kk] : Wwt[(n - 24) * IND + kk];
        __half h = __float2half_rn(v);
        g_Wow_hi[gid] = h;
        g_Wow_lo[gid] = __float2half_rn(v - __half2float(h));
    }
    if (gid < 32) g_bow[gid] = (gid < 24) ? bo[gid] : bw[gid - 24];
    if (gid < IND) {
        float sb = 0.0f;
        for (int n = 0; n < IND; n++) sb += Wout[gid * IND + n] * bv[n];
        g_bvout[gid] = sb;
    }
}

// ---------------- bilinear corner weights ----------------
__device__ __forceinline__ void bilerp_setup(float u, float v, int& i00, int& i01,
                                             int& i10, int& i11, float& w00, float& w01,
                                             float& w10, float& w11) {
    float x = __saturatef(u) * 127.0f;
    float y = __saturatef(v) * 127.0f;
    float xf = floorf(x), yf = floorf(y);
    int ix0 = (int)xf, iy0 = (int)yf;
    int ix1 = min(ix0 + 1, 127), iy1 = min(iy0 + 1, 127);
    float wx = x - xf, wy = y - yf;
    w00 = (1.0f - wx) * (1.0f - wy);
    w01 = wx * (1.0f - wy);
    w10 = (1.0f - wx) * wy;
    w11 = wx * wy;
    i00 = iy0 * RESOL + ix0; i01 = iy0 * RESOL + ix1;
    i10 = iy1 * RESOL + ix0; i11 = iy1 * RESOL + ix1;
}

// ---------------- 2) sample features at query points (fp32 planes) ----------------
__global__ __launch_bounds__(256) void sample_query(const float* __restrict__ qp) {
    int gid = blockIdx.x * 256 + threadIdx.x;
    int pt = gid / 24, lane = gid - pt * 24;
    int c8 = lane * 8;
    int p = c8 >> 6, ch = c8 & 63;
    int b = pt >> 14;
    float px = qp[pt * 3 + 0], py = qp[pt * 3 + 1], pz = qp[pt * 3 + 2];
    float u = (p == 2) ? py : px;
    float v = (p == 1) ? py : pz;
    int i00, i01, i10, i11;
    float w00, w01, w10, w11;
    bilerp_setup(u, v, i00, i01, i10, i11, w00, w01, w10, w11);
    const float* base = g_planesf + (size_t)(b * 3 + p) * HWSZ * CPL + ch;
    float acc[8];
#pragma unroll
    for (int h = 0; h < 2; h++) {
        float4 f00 = *(const float4*)(base + (size_t)i00 * CPL + 4 * h);
        float4 f01 = *(const float4*)(base + (size_t)i01 * CPL + 4 * h);
        float4 f10 = *(const float4*)(base + (size_t)i10 * CPL + 4 * h);
        float4 f11 = *(const float4*)(base + (size_t)i11 * CPL + 4 * h);
        acc[4 * h + 0] = w00 * f00.x + w01 * f01.x + w10 * f10.x + w11 * f11.x;
        acc[4 * h + 1] = w00 * f00.y + w01 * f01.y + w10 * f10.y + w11 * f11.y;
        acc[4 * h + 2] = w00 * f00.z + w01 * f01.z + w10 * f10.z + w11 * f11.z;
        acc[4 * h + 3] = w00 * f00.w + w01 * f01.w + w10 * f10.w + w11 * f11.w;
    }
    float4* o = (float4*)(g_feat + (size_t)pt * IND + c8);
    o[0] = make_float4(acc[0], acc[1], acc[2], acc[3]);
    o[1] = make_float4(acc[4], acc[5], acc[6], acc[7]);
}

// ---------------- MMA helpers ----------------
__device__ __forceinline__ void mma16816(float* c, const unsigned* a, const unsigned* b) {
    asm volatile(
        "mma.sync.aligned.m16n8k16.row.col.f32.f16.f16.f32 "
        "{%0,%1,%2,%3}, {%4,%5,%6,%7}, {%8,%9}, {%0,%1,%2,%3};\n"
        : "+f"(c[0]), "+f"(c[1]), "+f"(c[2]), "+f"(c[3])
        : "r"(a[0]), "r"(a[1]), "r"(a[2]), "r"(a[3]), "r"(b[0]), "r"(b[1]));
}
__device__ __forceinline__ void split2(float2 v, unsigned& hi, unsigned& lo) {
    __half2 h = __floats2half2_rn(v.x, v.y);
    float2 hf = __half22float2(h);
    __half2 l = __floats2half2_rn(v.x - hf.x, v.y - hf.y);
    hi = *(unsigned*)&h;
    lo = *(unsigned*)&l;
}
__device__ __forceinline__ void load_a_raw(const float* p, float2* buf) {
    buf[0] = *(const float2*)(p);
    buf[1] = *(const float2*)(p + 8 * IND);
    buf[2] = *(const float2*)(p + 8);
    buf[3] = *(const float2*)(p + 8 * IND + 8);
}

// ---------------- 3) off+wt predictor via split-fp16 MMA (smem B, dbuf A) --------
// POSITION PATH: keeps all 3 MMA terms (fp32-grade). M=NPTS, N=32, K=192.
__global__ __launch_bounds__(256) void predict_offwt_mma() {
    __shared__ __half Bs[2][32 * IND];   // [hi/lo][n][k], 4B-word XOR swizzle
    int tid = threadIdx.x, wid = tid >> 5, lane = tid & 31;
    int g = lane >> 2, t = lane & 3;
    int m_base = blockIdx.x * 256 + wid * 32;

    for (int idx = tid; idx < 32 * 24; idx += 256) {
        int n = idx / 24, c8 = idx - n * 24;
        int pw = (c8 * 4) ^ ((n & 7) << 2);
        int hoff = n * IND + (pw << 1);
        *(uint4*)(&Bs[0][hoff]) = *(const uint4*)(g_Wow_hi + (size_t)n * IND + c8 * 8);
        *(uint4*)(&Bs[1][hoff]) = *(const uint4*)(g_Wow_lo + (size_t)n * IND + c8 * 8);
    }
    __syncthreads();

    float c[2][4][4] = {};
    const float* Ap = g_feat + (size_t)(m_base + g) * IND + 2 * t;

    float2 abuf[2][2][4];
    load_a_raw(Ap, abuf[0][0]);
    load_a_raw(Ap + 16 * IND, abuf[0][1]);

    for (int kt = 0; kt < 12; kt++) {
        int cur = kt & 1;
        if (kt < 11) {
            int k1 = (kt + 1) * 16;
            load_a_raw(Ap + k1, abuf[cur ^ 1][0]);
            load_a_raw(Ap + 16 * IND + k1, abuf[cur ^ 1][1]);
        }
        int k0 = kt * 16;
        unsigned ah[2][4], al[2][4], bh[4][2], bl[4][2];
#pragma unroll
        for (int ms = 0; ms < 2; ms++)
#pragma unroll
            for (int i = 0; i < 4; i++)
                split2(abuf[cur][ms][i], ah[ms][i], al[ms][i]);
        int w0 = (k0 >> 1) + t;
#pragma unroll
        for (int ns = 0; ns < 4; ns++) {
            int n = ns * 8 + g;
            int sw = (n & 7) << 2;
            int h0 = n * IND + ((w0 ^ sw) << 1);
            int h1 = n * IND + (((w0 + 4) ^ sw) << 1);
            bh[ns][0] = *(const unsigned*)(&Bs[0][h0]);
            bh[ns][1] = *(const unsigned*)(&Bs[0][h1]);
            bl[ns][0] = *(const unsigned*)(&Bs[1][h0]);
            bl[ns][1] = *(const unsigned*)(&Bs[1][h1]);
        }
#pragma unroll
        for (int ms = 0; ms < 2; ms++)
#pragma unroll
            for (int ns = 0; ns < 4; ns++) {
                mma16816(c[ms][ns], ah[ms], bh[ns]);
                mma16816(c[ms][ns], ah[ms], bl[ns]);
                mma16816(c[ms][ns], al[ms], bh[ns]);
            }
    }

#pragma unroll
    for (int ms = 0; ms < 2; ms++) {
        int r0 = m_base + ms * 16 + g;
        int r1 = r0 + 8;
#pragma unroll
        for (int ns = 0; ns < 4; ns++) {
            int nc = ns * 8 + 2 * t;
            float b0 = g_bow[nc], b1 = g_bow[nc + 1];
            *(float2*)(g_offwt + (size_t)r0 * 32 + nc) =
                make_float2(c[ms][ns][0] + b0, c[ms][ns][1] + b1);
            *(float2*)(g_offwt + (size_t)r1 * 32 + nc) =
                make_float2(c[ms][ns][2] + b0, c[ms][ns][3] + b1);
        }
    }
}

// ---------------- 4) sample offset points (fp16 planes), smem offwt+qp -----------
// block 192 threads = 8 points x 24 lanes; fp16 output in PERMUTED frag order
// (R13-exact: lane = ch8, sequential s-loop, default reg allocation)
__global__ __launch_bounds__(192) void sample_aux(const float* __restrict__ qp) {
    __shared__ float4 sow4[64];          // 8 points x 32 floats
    __shared__ float sqp[24];            // 8 points x 3 coords
    int tid = threadIdx.x;
    int pt0 = blockIdx.x * 8;
    if (tid < 64) sow4[tid] = ((const float4*)(g_offwt + (size_t)pt0 * 32))[tid];
    if (tid >= 64 && tid < 88) sqp[tid - 64] = qp[pt0 * 3 + (tid - 64)];
    __syncthreads();
    const float* sow = (const float*)sow4;

    int pi = tid / 24, lane = tid - pi * 24;
    int pt = pt0 + pi;
    int c8 = lane * 8;
    int p = c8 >> 6, ch = c8 & 63;
    int b = pt >> 14;
    float px = sqp[pi * 3 + 0], py = sqp[pi * 3 + 1], pz = sqp[pi * 3 + 2];
    const float* ow = sow + pi * 32;

    const __half* base = g_planesh + (size_t)(b * 3 + p) * HWSZ * CPL + ch;
    float acc[8] = {};
#pragma unroll
    for (int s = 0; s < SSAMP; s++) {
        float qx = px + ow[s * 3 + 0];
        float qy = py + ow[s * 3 + 1];
        float qz = pz + ow[s * 3 + 2];
        float wgt = ow[24 + s];
        float u = (p == 2) ? qy : qx;
        float v = (p == 1) ? qy : qz;
        int i00, i01, i10, i11;
        float w00, w01, w10, w11;
        bilerp_setup(u, v, i00, i01, i10, i11, w00, w01, w10, w11);
        w00 *= wgt; w01 *= wgt; w10 *= wgt; w11 *= wgt;
        uint4 q00 = *(const uint4*)(base + (size_t)i00 * CPL);
        uint4 q01 = *(const uint4*)(base + (size_t)i01 * CPL);
        uint4 q10 = *(const uint4*)(base + (size_t)i10 * CPL);
        uint4 q11 = *(const uint4*)(base + (size_t)i11 * CPL);
        const __half2* h00 = (const __half2*)&q00;
        const __half2* h01 = (const __half2*)&q01;
        const __half2* h10 = (const __half2*)&q10;
        const __half2* h11 = (const __half2*)&q11;
#pragma unroll
        for (int i = 0; i < 4; i++) {
            float2 f00 = __half22float2(h00[i]);
            float2 f01 = __half22float2(h01[i]);
            float2 f10 = __half22float2(h10[i]);
            float2 f11 = __half22float2(h11[i]);
            acc[2 * i + 0] += w00 * f00.x + w01 * f01.x + w10 * f10.x + w11 * f11.x;
            acc[2 * i + 1] += w00 * f00.y + w01 * f01.y + w10 * f10.y + w11 * f11.y;
        }
    }
    // permuted fp16 store: element offsets blk+half + {0,1},{4,5},{8,9},{12,13}
    {
        int blk = c8 & ~15;
        int half = (c8 & 8) ? 2 : 0;
        __half* o = g_auxwh + (size_t)pt * IND + blk + half;
#pragma unroll
        for (int i = 0; i < 4; i++)
            *(__half2*)(o + 4 * i) = __floats2half2_rn(acc[2 * i], acc[2 * i + 1]);
    }
    if (lane == 0) {
        float wts = 0.0f;
#pragma unroll
        for (int s = 0; s < SSAMP; s++) wts += ow[24 + s];
        g_wtsum[pt] = wts;
    }
}

// ---------------- 5) fused GEMM: out = auxw@Wc^T + wts*bvout + bout + feat --------
// VALUE PATH: single MMA pass, A pre-rounded fp16 (R13-exact mainloop).
__global__ __launch_bounds__(256) void gemm_comb(const float* __restrict__ bout,
                                                 float* __restrict__ outF) {
    __shared__ __half Bs[64 * IND];
    int tid = threadIdx.x, wid = tid >> 5, lane = tid & 31;
    int g = lane >> 2, t = lane & 3;
    int m_base = blockIdx.x * 128 + (wid >> 1) * 32;
    int n_blk = blockIdx.y * 64;
    int nloc = (wid & 1) * 32;

    for (int idx = tid; idx < 64 * 24; idx += 256) {
        int n = idx / 24, c8 = idx - n * 24;
        int pw = (c8 * 4) ^ ((n & 7) << 2);
        int hoff = n * IND + (pw << 1);
        *(uint4*)(&Bs[hoff]) =
            *(const uint4*)(g_Wc_hi + (size_t)(n_blk + n) * IND + c8 * 8);
    }
    __syncthreads();

    float c[2][4][4] = {};
    const __half* Ap = g_auxwh + (size_t)(m_base + g) * IND + 4 * t;

    uint2 abuf[2][2];
    abuf[0][0] = *(const uint2*)(Ap);
    abuf[0][1] = *(const uint2*)(Ap + 16 * IND);

    for (int kt = 0; kt < 12; kt++) {
        int cur = kt & 1;
        if (kt < 11) {
            int k1 = (kt + 1) * 16;
            abuf[cur ^ 1][0] = *(const uint2*)(Ap + k1);
            abuf[cur ^ 1][1] = *(const uint2*)(Ap + 16 * IND + k1);
        }
        int k0 = kt * 16;
        unsigned ah[2][4], bh[4][2];
#pragma unroll
        for (int ms = 0; ms < 2; ms++) {
            ah[ms][0] = abuf[cur][ms].x;
            ah[ms][2] = abuf[cur][ms].y;
        }
        {
            uint2 r8a = *(const uint2*)(Ap + 8 * IND + k0);
            uint2 r8b = *(const uint2*)(Ap + 24 * IND + k0);
            ah[0][1] = r8a.x; ah[0][3] = r8a.y;
            ah[1][1] = r8b.x; ah[1][3] = r8b.y;
        }
        int w0 = (k0 >> 1) + t;
#pragma unroll
        for (int ns = 0; ns < 4; ns++) {
            int n = nloc + ns * 8 + g;
            int sw = (n & 7) << 2;
            int h0 = n * IND + ((w0 ^ sw) << 1);
            int h1 = n * IND + (((w0 + 4) ^ sw) << 1);
            bh[ns][0] = *(const unsigned*)(&Bs[h0]);
            bh[ns][1] = *(const unsigned*)(&Bs[h1]);
        }
#pragma unroll
        for (int ms = 0; ms < 2; ms++)
#pragma unroll
            for (int ns = 0; ns < 4; ns++)
                mma16816(c[ms][ns], ah[ms], bh[ns]);
    }

    int n_base = n_blk + nloc;
#pragma unroll
    for (int ms = 0; ms < 2; ms++) {
        int r0 = m_base + ms * 16 + g;
        int r1 = r0 + 8;
        float rs0 = g_wtsum[r0], rs1 = g_wtsum[r1];
#pragma unroll
        for (int ns = 0; ns < 4; ns++) {
            int nc = n_base + ns * 8 + 2 * t;
            float bo0 = bout[nc], bo1 = bout[nc + 1];
            float bv0 = g_bvout[nc], bv1 = g_bvout[nc + 1];
            size_t o0 = (size_t)r0 * IND + nc;
            size_t o1 = (size_t)r1 * IND + nc;
            float2 f0 = *(const float2*)(g_feat + o0);
            float2 f1 = *(const float2*)(g_feat + o1);
            *(float2*)(outF + o0) = make_float2(
                c[ms][ns][0] + bv0 * rs0 + bo0 + f0.x,
                c[ms][ns][1] + bv1 * rs0 + bo1 + f0.y);
            *(float2*)(outF + o1) = make_float2(
                c[ms][ns][2] + bv0 * rs1 + bo0 + f1.x,
                c[ms][ns][3] + bv1 * rs1 + bo1 + f1.y);
        }
    }
}

// ---------------- launch ----------------
extern "C" void kernel_launch(void* const* d_in, const int* in_sizes, int n_in,
                              void* d_out, int out_size) {
    const float* qp    = (const float*)d_in[0];
    const float* fxz   = (const float*)d_in[1];
    const float* fxy   = (const float*)d_in[2];
    const float* fyz   = (const float*)d_in[3];
    const float* W_v   = (const float*)d_in[4];
    const float* b_v   = (const float*)d_in[5];
    const float* W_out = (const float*)d_in[6];
    const float* b_out = (const float*)d_in[7];
    const float* W_off = (const float*)d_in[8];
    const float* b_off = (const float*)d_in[9];
    const float* W_wt  = (const float*)d_in[10];
    const float* b_wt  = (const float*)d_in[11];
    float* out = (float*)d_out;

    transpose_planes<<<dim3(HWSZ / 128, BSZ, 3), 256>>>(fxz, fxy, fyz);
    prep_weights<<<IND, IND>>>(W_out, W_v, W_off, b_off, W_wt, b_wt, b_v);
    sample_query<<<NPTS * 24 / 256, 256>>>(qp);
    predict_offwt_mma<<<NPTS / 256, 256>>>();
    sample_aux<<<NPTS / 8, 192>>>(qp);
    gemm_comb<<<dim3(NPTS / 128, 3), 256>>>(b_out, out);
}